// round 1
// baseline (speedup 1.0000x reference)
#include <cuda_runtime.h>
#include <math.h>

#define D_MODEL 1024
#define NUM_HEADS 16
#define DK 64
#define SEQ 2048
#define BATCH 2
#define MROWS (BATCH * SEQ)  // 4096

// Scratch buffers (device globals — no allocation allowed)
__device__ float g_Q[MROWS * D_MODEL];
__device__ float g_K[MROWS * D_MODEL];
__device__ float g_V[MROWS * D_MODEL];
__device__ float g_O[MROWS * D_MODEL];

// ---------------------------------------------------------------------------
// C[M][N] = X[M][K] * W[N][K]^T   (both operands K-contiguous, "NT" GEMM)
// BM=BN=64, BK=32, 256 threads, 4x4 micro-tile per thread.
// Tiles stored k-major in smem so inner loop is 16 FFMA + 2 LDS.128.
// ---------------------------------------------------------------------------
__global__ __launch_bounds__(256) void gemm_nt(const float* __restrict__ X,
                                               const float* __restrict__ W,
                                               float* __restrict__ C,
                                               int M, int N, int K) {
    __shared__ float Xs[32][68];  // [k][m], pitch 68 (16B-aligned float4 rows)
    __shared__ float Ws[32][68];  // [k][n]

    const int tid = threadIdx.x;
    const int tx = tid & 15;       // col group (4 cols)
    const int ty = tid >> 4;       // row group (4 rows)
    const int m0 = blockIdx.y * 64;
    const int n0 = blockIdx.x * 64;

    float acc[4][4] = {};

    for (int k0 = 0; k0 < K; k0 += 32) {
        __syncthreads();
#pragma unroll
        for (int it = 0; it < 2; it++) {
            int idx = tid + it * 256;      // 0..511
            int r = idx >> 3;              // 0..63 (row of the 64-row tile)
            int c = (idx & 7) << 2;        // 0..28 (k within tile, float4)
            float4 xv = *(const float4*)&X[(size_t)(m0 + r) * K + k0 + c];
            Xs[c + 0][r] = xv.x; Xs[c + 1][r] = xv.y;
            Xs[c + 2][r] = xv.z; Xs[c + 3][r] = xv.w;
            float4 wv = *(const float4*)&W[(size_t)(n0 + r) * K + k0 + c];
            Ws[c + 0][r] = wv.x; Ws[c + 1][r] = wv.y;
            Ws[c + 2][r] = wv.z; Ws[c + 3][r] = wv.w;
        }
        __syncthreads();
#pragma unroll
        for (int k = 0; k < 32; k++) {
            float4 a = *(const float4*)&Xs[k][ty << 2];
            float4 b = *(const float4*)&Ws[k][tx << 2];
            acc[0][0] += a.x * b.x; acc[0][1] += a.x * b.y;
            acc[0][2] += a.x * b.z; acc[0][3] += a.x * b.w;
            acc[1][0] += a.y * b.x; acc[1][1] += a.y * b.y;
            acc[1][2] += a.y * b.z; acc[1][3] += a.y * b.w;
            acc[2][0] += a.z * b.x; acc[2][1] += a.z * b.y;
            acc[2][2] += a.z * b.z; acc[2][3] += a.z * b.w;
            acc[3][0] += a.w * b.x; acc[3][1] += a.w * b.y;
            acc[3][2] += a.w * b.z; acc[3][3] += a.w * b.w;
        }
    }

#pragma unroll
    for (int i = 0; i < 4; i++) {
        float4 v = make_float4(acc[i][0], acc[i][1], acc[i][2], acc[i][3]);
        *(float4*)&C[(size_t)(m0 + 4 * ty + i) * N + n0 + 4 * tx] = v;
    }
}

// ---------------------------------------------------------------------------
// RoPE in-place on Q and K in linear (B*S, D) layout.
// One thread per complex pair per row, applied to both Q and K.
// ---------------------------------------------------------------------------
__global__ __launch_bounds__(256) void rope_kernel(float* __restrict__ Q,
                                                   float* __restrict__ K,
                                                   const int* __restrict__ pos) {
    int idx = blockIdx.x * 256 + threadIdx.x;   // over MROWS * 512 pairs
    int row = idx >> 9;                         // b*SEQ + s
    int pc = idx & 511;                         // h*32 + p
    int p = pc & 31;                            // pair index within head
    int s = row & (SEQ - 1);

    // inv_freq = exp(-p * ln(10000)/32)
    float inv = expf((float)p * -0.28782313662425572f);
    float ang = (float)pos[s] * inv;
    float sv, cv;
    sincosf(ang, &sv, &cv);

    size_t off = (size_t)row * D_MODEL + 2 * pc;
    float2 q = *(float2*)&Q[off];
    float2 k = *(float2*)&K[off];
    float2 qo = make_float2(q.x * cv - q.y * sv, q.x * sv + q.y * cv);
    float2 ko = make_float2(k.x * cv - k.y * sv, k.x * sv + k.y * cv);
    *(float2*)&Q[off] = qo;
    *(float2*)&K[off] = ko;
}

// ---------------------------------------------------------------------------
// Causal flash attention.
// Grid: (S/64 q-tiles, B*H). Block: 256 threads.
// Bq=64, Bk=32, dk=64. O kept in registers (4x4 per thread), online softmax.
// Reads Q/K/V directly from linear (B*S, D) layout (head slice strided).
// ---------------------------------------------------------------------------
__global__ __launch_bounds__(256) void attn_kernel(const float* __restrict__ Q,
                                                   const float* __restrict__ K,
                                                   const float* __restrict__ V,
                                                   float* __restrict__ O) {
    __shared__ float Qs[64][65];
    __shared__ float Ks[32][65];
    __shared__ float Vs[32][65];
    __shared__ float Ps[64][33];
    __shared__ float sm_m[64], sm_l[64], sm_r[64];

    const int tid = threadIdx.x;
    const int tx = tid & 15;
    const int ty = tid >> 4;
    const int bh = blockIdx.y;
    const int b = bh >> 4;
    const int h = bh & 15;
    // reverse q-tile order: heavy (long-context) tiles launch first
    const int qt = (SEQ / 64 - 1) - blockIdx.x;
    const int q0 = qt * 64;

    const float* Qb = Q + (size_t)b * SEQ * D_MODEL + h * DK;
    const float* Kb = K + (size_t)b * SEQ * D_MODEL + h * DK;
    const float* Vb = V + (size_t)b * SEQ * D_MODEL + h * DK;
    float* Ob = O + (size_t)b * SEQ * D_MODEL + h * DK;

    // Load Q tile (64 x 64)
#pragma unroll
    for (int it = 0; it < 4; it++) {
        int idx = tid + it * 256;
        int r = idx >> 4;
        int c = (idx & 15) << 2;
        float4 v = *(const float4*)&Qb[(size_t)(q0 + r) * D_MODEL + c];
        Qs[r][c] = v.x; Qs[r][c + 1] = v.y; Qs[r][c + 2] = v.z; Qs[r][c + 3] = v.w;
    }
    if (tid < 64) { sm_m[tid] = -1e30f; sm_l[tid] = 0.f; }

    float acc[4][4] = {};
    const int nkt = (q0 + 64) >> 5;

    for (int kt = 0; kt < nkt; kt++) {
        const int k0 = kt << 5;
        __syncthreads();   // protect Ks/Vs/Ps still being read last iteration
#pragma unroll
        for (int it = 0; it < 2; it++) {
            int idx = tid + it * 256;
            int r = idx >> 4;
            int c = (idx & 15) << 2;
            float4 kv = *(const float4*)&Kb[(size_t)(k0 + r) * D_MODEL + c];
            Ks[r][c] = kv.x; Ks[r][c + 1] = kv.y; Ks[r][c + 2] = kv.z; Ks[r][c + 3] = kv.w;
            float4 vv = *(const float4*)&Vb[(size_t)(k0 + r) * D_MODEL + c];
            Vs[r][c] = vv.x; Vs[r][c + 1] = vv.y; Vs[r][c + 2] = vv.z; Vs[r][c + 3] = vv.w;
        }
        __syncthreads();

        // Phase 1: S = Q K^T  (64x32 tile), 4x2 micro-tile per thread
        float sacc[4][2] = {};
#pragma unroll 16
        for (int d = 0; d < 64; d++) {
            float b0 = Ks[2 * tx + 0][d];
            float b1 = Ks[2 * tx + 1][d];
#pragma unroll
            for (int i = 0; i < 4; i++) {
                float a = Qs[4 * ty + i][d];
                sacc[i][0] += a * b0;
                sacc[i][1] += a * b1;
            }
        }
#pragma unroll
        for (int i = 0; i < 4; i++) {
            int r = 4 * ty + i;
#pragma unroll
            for (int j = 0; j < 2; j++) {
                int c = 2 * tx + j;
                float v = sacc[i][j] * 0.125f;   // 1/sqrt(64)
                if (k0 + c > q0 + r) v = -1e30f; // causal mask
                Ps[r][c] = v;
            }
        }
        __syncthreads();

        // Online softmax update: thread i handles row i
        if (tid < 64) {
            float m_old = sm_m[tid];
            float mx = m_old;
#pragma unroll
            for (int j = 0; j < 32; j++) mx = fmaxf(mx, Ps[tid][j]);
            float rs = expf(m_old - mx);
            float sum = 0.f;
#pragma unroll
            for (int j = 0; j < 32; j++) {
                float pv = expf(Ps[tid][j] - mx);
                Ps[tid][j] = pv;
                sum += pv;
            }
            sm_m[tid] = mx;
            sm_l[tid] = sm_l[tid] * rs + sum;
            sm_r[tid] = rs;
        }
        __syncthreads();

        // Rescale O and accumulate P @ V
        float r0 = sm_r[4 * ty + 0], r1 = sm_r[4 * ty + 1];
        float r2 = sm_r[4 * ty + 2], r3 = sm_r[4 * ty + 3];
#pragma unroll
        for (int j = 0; j < 4; j++) {
            acc[0][j] *= r0; acc[1][j] *= r1; acc[2][j] *= r2; acc[3][j] *= r3;
        }
#pragma unroll 8
        for (int j = 0; j < 32; j++) {
            float b0 = Vs[j][4 * tx + 0], b1 = Vs[j][4 * tx + 1];
            float b2 = Vs[j][4 * tx + 2], b3 = Vs[j][4 * tx + 3];
#pragma unroll
            for (int i = 0; i < 4; i++) {
                float a = Ps[4 * ty + i][j];
                acc[i][0] += a * b0; acc[i][1] += a * b1;
                acc[i][2] += a * b2; acc[i][3] += a * b3;
            }
        }
    }

    // Finalize: divide by softmax denominator, store
#pragma unroll
    for (int i = 0; i < 4; i++) {
        float invl = 1.f / sm_l[4 * ty + i];
        float4 v = make_float4(acc[i][0] * invl, acc[i][1] * invl,
                               acc[i][2] * invl, acc[i][3] * invl);
        *(float4*)&Ob[(size_t)(q0 + 4 * ty + i) * D_MODEL + 4 * tx] = v;
    }
}

// ---------------------------------------------------------------------------
extern "C" void kernel_launch(void* const* d_in, const int* in_sizes, int n_in,
                              void* d_out, int out_size) {
    const float* x  = (const float*)d_in[0];
    const int*   ps = (const int*)d_in[1];
    const float* Wq = (const float*)d_in[2];
    const float* Wk = (const float*)d_in[3];
    const float* Wv = (const float*)d_in[4];
    const float* Wo = (const float*)d_in[5];
    float* out = (float*)d_out;

    float *gq, *gk, *gv, *go;
    cudaGetSymbolAddress((void**)&gq, g_Q);
    cudaGetSymbolAddress((void**)&gk, g_K);
    cudaGetSymbolAddress((void**)&gv, g_V);
    cudaGetSymbolAddress((void**)&go, g_O);

    dim3 gg(D_MODEL / 64, MROWS / 64);   // (16, 64)
    gemm_nt<<<gg, 256>>>(x, Wq, gq, MROWS, D_MODEL, D_MODEL);
    gemm_nt<<<gg, 256>>>(x, Wk, gk, MROWS, D_MODEL, D_MODEL);
    gemm_nt<<<gg, 256>>>(x, Wv, gv, MROWS, D_MODEL, D_MODEL);

    rope_kernel<<<(MROWS * 512) / 256, 256>>>(gq, gk, ps);

    attn_kernel<<<dim3(SEQ / 64, BATCH * NUM_HEADS), 256>>>(gq, gk, gv, go);

    gemm_nt<<<gg, 256>>>(go, Wo, out, MROWS, D_MODEL, D_MODEL);
}

// round 2
// speedup vs baseline: 1.5847x; 1.5847x over previous
#include <cuda_runtime.h>
#include <math.h>

#define D_MODEL 1024
#define NUM_HEADS 16
#define DK 64
#define SEQ 2048
#define BATCH 2
#define MROWS (BATCH * SEQ)  // 4096

// Scratch buffers (device globals — no allocation allowed)
__device__ float g_Q[MROWS * D_MODEL];
__device__ float g_K[MROWS * D_MODEL];
__device__ float g_V[MROWS * D_MODEL];
__device__ float g_O[MROWS * D_MODEL];

// ---------------------------------------------------------------------------
// TF32 tensor-core GEMM:  C[M][N] = X[M][K] * W[N][K]^T   (NT)
// BM=128, BN=128, BK=16. 256 threads = 8 warps in 2x4 grid, warp tile 64x32.
// mma.sync.aligned.m16n8k8.row.col.f32.tf32.tf32.f32
//
// Smem layout: per row (pitch 24 u32), logical k-col L in [0,16) stored at
// physical P = 8*(L>>3) + 2*(L&3) + (((L&7))>>2). This puts cols (q, q+4)
// adjacent so an A/B fragment half is ONE LDS.64, conflict-free at pitch 24.
// ---------------------------------------------------------------------------
__device__ __forceinline__ unsigned f2tf32(float v) {
    unsigned u;
    asm("cvt.rna.tf32.f32 %0, %1;" : "=r"(u) : "f"(v));
    return u;
}

__global__ __launch_bounds__(256) void gemm_tf32(const float* __restrict__ X,
                                                 const float* __restrict__ W,
                                                 float* __restrict__ C,
                                                 int M, int N, int K) {
    __shared__ unsigned As[128 * 24];
    __shared__ unsigned Bs[128 * 24];

    const int tid = threadIdx.x;
    const int lane = tid & 31;
    const int wid = tid >> 5;
    const int wr = wid >> 2;        // warp row 0..1  (64 rows each)
    const int wc = wid & 3;         // warp col 0..3  (32 cols each)
    const int m0 = blockIdx.y * 128;
    const int n0 = blockIdx.x * 128;

    const int g = lane >> 2;        // fragment row group 0..7
    const int q = lane & 3;         // fragment quad 0..3

    // gmem staging: 2 float4 each for A and B per thread per iter
    // idx = tid + it*256; r = idx>>2 (0..127), c = idx&3 (float4 col)
    float4 xa[2], xb[2];

    auto load_g = [&](int k0) {
#pragma unroll
        for (int it = 0; it < 2; it++) {
            int idx = tid + it * 256;
            int r = idx >> 2;
            int c = idx & 3;
            xa[it] = *(const float4*)&X[(size_t)(m0 + r) * K + k0 + 4 * c];
            xb[it] = *(const float4*)&W[(size_t)(n0 + r) * K + k0 + 4 * c];
        }
    };
    auto store_s = [&]() {
#pragma unroll
        for (int it = 0; it < 2; it++) {
            int idx = tid + it * 256;
            int r = idx >> 2;
            int c = idx & 3;
            int base = r * 24 + 8 * (c >> 1) + (c & 1);
            float va[4] = {xa[it].x, xa[it].y, xa[it].z, xa[it].w};
            float vb[4] = {xb[it].x, xb[it].y, xb[it].z, xb[it].w};
#pragma unroll
            for (int j = 0; j < 4; j++) {
                As[base + 2 * j] = f2tf32(va[j]);
                Bs[base + 2 * j] = f2tf32(vb[j]);
            }
        }
    };

    float acc[16][4] = {};

    load_g(0);
    store_s();
    __syncthreads();

    for (int k0 = 16;; k0 += 16) {
        const bool last = (k0 >= K);
        if (!last) load_g(k0);

        // compute 2 k-slices from smem
#pragma unroll
        for (int s = 0; s < 2; s++) {
            unsigned af[4][4];   // [m-tile][4 regs]
            unsigned bf[4][2];   // [n-tile][2 regs]
#pragma unroll
            for (int i = 0; i < 4; i++) {
                int arow = wr * 64 + i * 16 + g;
                uint2 lo = *(const uint2*)&As[arow * 24 + 8 * s + 2 * q];
                uint2 hi = *(const uint2*)&As[(arow + 8) * 24 + 8 * s + 2 * q];
                af[i][0] = lo.x; af[i][1] = hi.x; af[i][2] = lo.y; af[i][3] = hi.y;
            }
#pragma unroll
            for (int j = 0; j < 4; j++) {
                int brow = wc * 32 + j * 8 + g;
                uint2 bb = *(const uint2*)&Bs[brow * 24 + 8 * s + 2 * q];
                bf[j][0] = bb.x; bf[j][1] = bb.y;
            }
#pragma unroll
            for (int i = 0; i < 4; i++) {
#pragma unroll
                for (int j = 0; j < 4; j++) {
                    float* d = acc[i * 4 + j];
                    asm volatile(
                        "mma.sync.aligned.m16n8k8.row.col.f32.tf32.tf32.f32 "
                        "{%0,%1,%2,%3}, {%4,%5,%6,%7}, {%8,%9}, {%0,%1,%2,%3};\n"
                        : "+f"(d[0]), "+f"(d[1]), "+f"(d[2]), "+f"(d[3])
                        : "r"(af[i][0]), "r"(af[i][1]), "r"(af[i][2]), "r"(af[i][3]),
                          "r"(bf[j][0]), "r"(bf[j][1]));
                }
            }
        }

        __syncthreads();
        if (last) break;
        store_s();
        __syncthreads();
    }

    // Epilogue: c0,c1 at (row, col), c2,c3 at (row+8, col); col pair contiguous
#pragma unroll
    for (int i = 0; i < 4; i++) {
        int row = m0 + wr * 64 + i * 16 + g;
#pragma unroll
        for (int j = 0; j < 4; j++) {
            int col = n0 + wc * 32 + j * 8 + 2 * q;
            float* d = acc[i * 4 + j];
            *(float2*)&C[(size_t)row * N + col] = make_float2(d[0], d[1]);
            *(float2*)&C[(size_t)(row + 8) * N + col] = make_float2(d[2], d[3]);
        }
    }
}

// ---------------------------------------------------------------------------
// RoPE in-place on Q and K in linear (B*S, D) layout.
// ---------------------------------------------------------------------------
__global__ __launch_bounds__(256) void rope_kernel(float* __restrict__ Q,
                                                   float* __restrict__ K,
                                                   const int* __restrict__ pos) {
    int idx = blockIdx.x * 256 + threadIdx.x;   // over MROWS * 512 pairs
    int row = idx >> 9;                         // b*SEQ + s
    int pc = idx & 511;                         // h*32 + p
    int p = pc & 31;                            // pair index within head
    int s = row & (SEQ - 1);

    float inv = expf((float)p * -0.28782313662425572f);  // ln(10000)/32
    float ang = (float)pos[s] * inv;
    float sv, cv;
    sincosf(ang, &sv, &cv);

    size_t off = (size_t)row * D_MODEL + 2 * pc;
    float2 q = *(float2*)&Q[off];
    float2 k = *(float2*)&K[off];
    float2 qo = make_float2(q.x * cv - q.y * sv, q.x * sv + q.y * cv);
    float2 ko = make_float2(k.x * cv - k.y * sv, k.x * sv + k.y * cv);
    *(float2*)&Q[off] = qo;
    *(float2*)&K[off] = ko;
}

// ---------------------------------------------------------------------------
// Causal flash attention (fp32, unchanged this round).
// ---------------------------------------------------------------------------
__global__ __launch_bounds__(256) void attn_kernel(const float* __restrict__ Q,
                                                   const float* __restrict__ K,
                                                   const float* __restrict__ V,
                                                   float* __restrict__ O) {
    __shared__ float Qs[64][65];
    __shared__ float Ks[32][65];
    __shared__ float Vs[32][65];
    __shared__ float Ps[64][33];
    __shared__ float sm_m[64], sm_l[64], sm_r[64];

    const int tid = threadIdx.x;
    const int tx = tid & 15;
    const int ty = tid >> 4;
    const int bh = blockIdx.y;
    const int b = bh >> 4;
    const int h = bh & 15;
    const int qt = (SEQ / 64 - 1) - blockIdx.x;
    const int q0 = qt * 64;

    const float* Qb = Q + (size_t)b * SEQ * D_MODEL + h * DK;
    const float* Kb = K + (size_t)b * SEQ * D_MODEL + h * DK;
    const float* Vb = V + (size_t)b * SEQ * D_MODEL + h * DK;
    float* Ob = O + (size_t)b * SEQ * D_MODEL + h * DK;

#pragma unroll
    for (int it = 0; it < 4; it++) {
        int idx = tid + it * 256;
        int r = idx >> 4;
        int c = (idx & 15) << 2;
        float4 v = *(const float4*)&Qb[(size_t)(q0 + r) * D_MODEL + c];
        Qs[r][c] = v.x; Qs[r][c + 1] = v.y; Qs[r][c + 2] = v.z; Qs[r][c + 3] = v.w;
    }
    if (tid < 64) { sm_m[tid] = -1e30f; sm_l[tid] = 0.f; }

    float acc[4][4] = {};
    const int nkt = (q0 + 64) >> 5;

    for (int kt = 0; kt < nkt; kt++) {
        const int k0 = kt << 5;
        __syncthreads();
#pragma unroll
        for (int it = 0; it < 2; it++) {
            int idx = tid + it * 256;
            int r = idx >> 4;
            int c = (idx & 15) << 2;
            float4 kv = *(const float4*)&Kb[(size_t)(k0 + r) * D_MODEL + c];
            Ks[r][c] = kv.x; Ks[r][c + 1] = kv.y; Ks[r][c + 2] = kv.z; Ks[r][c + 3] = kv.w;
            float4 vv = *(const float4*)&Vb[(size_t)(k0 + r) * D_MODEL + c];
            Vs[r][c] = vv.x; Vs[r][c + 1] = vv.y; Vs[r][c + 2] = vv.z; Vs[r][c + 3] = vv.w;
        }
        __syncthreads();

        float sacc[4][2] = {};
#pragma unroll 16
        for (int d = 0; d < 64; d++) {
            float b0 = Ks[2 * tx + 0][d];
            float b1 = Ks[2 * tx + 1][d];
#pragma unroll
            for (int i = 0; i < 4; i++) {
                float a = Qs[4 * ty + i][d];
                sacc[i][0] += a * b0;
                sacc[i][1] += a * b1;
            }
        }
#pragma unroll
        for (int i = 0; i < 4; i++) {
            int r = 4 * ty + i;
#pragma unroll
            for (int j = 0; j < 2; j++) {
                int c = 2 * tx + j;
                float v = sacc[i][j] * 0.125f;
                if (k0 + c > q0 + r) v = -1e30f;
                Ps[r][c] = v;
            }
        }
        __syncthreads();

        if (tid < 64) {
            float m_old = sm_m[tid];
            float mx = m_old;
#pragma unroll
            for (int j = 0; j < 32; j++) mx = fmaxf(mx, Ps[tid][j]);
            float rs = expf(m_old - mx);
            float sum = 0.f;
#pragma unroll
            for (int j = 0; j < 32; j++) {
                float pv = expf(Ps[tid][j] - mx);
                Ps[tid][j] = pv;
                sum += pv;
            }
            sm_m[tid] = mx;
            sm_l[tid] = sm_l[tid] * rs + sum;
            sm_r[tid] = rs;
        }
        __syncthreads();

        float r0 = sm_r[4 * ty + 0], r1 = sm_r[4 * ty + 1];
        float r2 = sm_r[4 * ty + 2], r3 = sm_r[4 * ty + 3];
#pragma unroll
        for (int j = 0; j < 4; j++) {
            acc[0][j] *= r0; acc[1][j] *= r1; acc[2][j] *= r2; acc[3][j] *= r3;
        }
#pragma unroll 8
        for (int j = 0; j < 32; j++) {
            float b0 = Vs[j][4 * tx + 0], b1 = Vs[j][4 * tx + 1];
            float b2 = Vs[j][4 * tx + 2], b3 = Vs[j][4 * tx + 3];
#pragma unroll
            for (int i = 0; i < 4; i++) {
                float a = Ps[4 * ty + i][j];
                acc[i][0] += a * b0; acc[i][1] += a * b1;
                acc[i][2] += a * b2; acc[i][3] += a * b3;
            }
        }
    }

#pragma unroll
    for (int i = 0; i < 4; i++) {
        float invl = 1.f / sm_l[4 * ty + i];
        float4 v = make_float4(acc[i][0] * invl, acc[i][1] * invl,
                               acc[i][2] * invl, acc[i][3] * invl);
        *(float4*)&Ob[(size_t)(q0 + 4 * ty + i) * D_MODEL + 4 * tx] = v;
    }
}

// ---------------------------------------------------------------------------
extern "C" void kernel_launch(void* const* d_in, const int* in_sizes, int n_in,
                              void* d_out, int out_size) {
    const float* x  = (const float*)d_in[0];
    const int*   ps = (const int*)d_in[1];
    const float* Wq = (const float*)d_in[2];
    const float* Wk = (const float*)d_in[3];
    const float* Wv = (const float*)d_in[4];
    const float* Wo = (const float*)d_in[5];
    float* out = (float*)d_out;

    float *gq, *gk, *gv, *go;
    cudaGetSymbolAddress((void**)&gq, g_Q);
    cudaGetSymbolAddress((void**)&gk, g_K);
    cudaGetSymbolAddress((void**)&gv, g_V);
    cudaGetSymbolAddress((void**)&go, g_O);

    dim3 gg(D_MODEL / 128, MROWS / 128);   // (8, 32)
    gemm_tf32<<<gg, 256>>>(x, Wq, gq, MROWS, D_MODEL, D_MODEL);
    gemm_tf32<<<gg, 256>>>(x, Wk, gk, MROWS, D_MODEL, D_MODEL);
    gemm_tf32<<<gg, 256>>>(x, Wv, gv, MROWS, D_MODEL, D_MODEL);

    rope_kernel<<<(MROWS * 512) / 256, 256>>>(gq, gk, ps);

    attn_kernel<<<dim3(SEQ / 64, BATCH * NUM_HEADS), 256>>>(gq, gk, gv, go);

    gemm_tf32<<<gg, 256>>>(go, Wo, out, MROWS, D_MODEL, D_MODEL);
}

// round 3
// speedup vs baseline: 2.5588x; 1.6147x over previous
#include <cuda_runtime.h>
#include <math.h>

#define D_MODEL 1024
#define NUM_HEADS 16
#define DK 64
#define SEQ 2048
#define BATCH 2
#define MROWS (BATCH * SEQ)  // 4096
#define LOG2EF 1.4426950408889634f

// Scratch buffers (device globals — no allocation allowed)
__device__ float g_Q[MROWS * D_MODEL];
__device__ float g_K[MROWS * D_MODEL];
__device__ float g_V[MROWS * D_MODEL];
__device__ float g_O[MROWS * D_MODEL];

__device__ __forceinline__ unsigned f2tf32(float v) {
    unsigned u;
    asm("cvt.rna.tf32.f32 %0, %1;" : "=r"(u) : "f"(v));
    return u;
}

#define MMA_TF32(D, A, B)                                                     \
    asm volatile(                                                             \
        "mma.sync.aligned.m16n8k8.row.col.f32.tf32.tf32.f32 "                 \
        "{%0,%1,%2,%3}, {%4,%5,%6,%7}, {%8,%9}, {%0,%1,%2,%3};\n"             \
        : "+f"((D)[0]), "+f"((D)[1]), "+f"((D)[2]), "+f"((D)[3])              \
        : "r"((A)[0]), "r"((A)[1]), "r"((A)[2]), "r"((A)[3]),                 \
          "r"((B).x), "r"((B).y))

// ---------------------------------------------------------------------------
// TF32 tensor-core GEMM:  C[M][N] = X[M][K] * W[N][K]^T   (NT)
// BM=128, BN=128, BK=16. 256 threads = 8 warps in 2x4 grid, warp tile 64x32.
// ---------------------------------------------------------------------------
__global__ __launch_bounds__(256) void gemm_tf32(const float* __restrict__ X,
                                                 const float* __restrict__ W,
                                                 float* __restrict__ C,
                                                 int M, int N, int K) {
    __shared__ unsigned As[128 * 24];
    __shared__ unsigned Bs[128 * 24];

    const int tid = threadIdx.x;
    const int lane = tid & 31;
    const int wid = tid >> 5;
    const int wr = wid >> 2;
    const int wc = wid & 3;
    const int m0 = blockIdx.y * 128;
    const int n0 = blockIdx.x * 128;

    const int g = lane >> 2;
    const int q = lane & 3;

    float4 xa[2], xb[2];

    auto load_g = [&](int k0) {
#pragma unroll
        for (int it = 0; it < 2; it++) {
            int idx = tid + it * 256;
            int r = idx >> 2;
            int c = idx & 3;
            xa[it] = *(const float4*)&X[(size_t)(m0 + r) * K + k0 + 4 * c];
            xb[it] = *(const float4*)&W[(size_t)(n0 + r) * K + k0 + 4 * c];
        }
    };
    auto store_s = [&]() {
#pragma unroll
        for (int it = 0; it < 2; it++) {
            int idx = tid + it * 256;
            int r = idx >> 2;
            int c = idx & 3;
            int base = r * 24 + 8 * (c >> 1) + (c & 1);
            float va[4] = {xa[it].x, xa[it].y, xa[it].z, xa[it].w};
            float vb[4] = {xb[it].x, xb[it].y, xb[it].z, xb[it].w};
#pragma unroll
            for (int j = 0; j < 4; j++) {
                As[base + 2 * j] = f2tf32(va[j]);
                Bs[base + 2 * j] = f2tf32(vb[j]);
            }
        }
    };

    float acc[16][4] = {};

    load_g(0);
    store_s();
    __syncthreads();

    for (int k0 = 16;; k0 += 16) {
        const bool last = (k0 >= K);
        if (!last) load_g(k0);

#pragma unroll
        for (int s = 0; s < 2; s++) {
            unsigned af[4][4];
            uint2 bf[4];
#pragma unroll
            for (int i = 0; i < 4; i++) {
                int arow = wr * 64 + i * 16 + g;
                uint2 lo = *(const uint2*)&As[arow * 24 + 8 * s + 2 * q];
                uint2 hi = *(const uint2*)&As[(arow + 8) * 24 + 8 * s + 2 * q];
                af[i][0] = lo.x; af[i][1] = hi.x; af[i][2] = lo.y; af[i][3] = hi.y;
            }
#pragma unroll
            for (int j = 0; j < 4; j++) {
                int brow = wc * 32 + j * 8 + g;
                bf[j] = *(const uint2*)&Bs[brow * 24 + 8 * s + 2 * q];
            }
#pragma unroll
            for (int i = 0; i < 4; i++) {
#pragma unroll
                for (int j = 0; j < 4; j++) {
                    MMA_TF32(acc[i * 4 + j], af[i], bf[j]);
                }
            }
        }

        __syncthreads();
        if (last) break;
        store_s();
        __syncthreads();
    }

#pragma unroll
    for (int i = 0; i < 4; i++) {
        int row = m0 + wr * 64 + i * 16 + g;
#pragma unroll
        for (int j = 0; j < 4; j++) {
            int col = n0 + wc * 32 + j * 8 + 2 * q;
            float* d = acc[i * 4 + j];
            *(float2*)&C[(size_t)row * N + col] = make_float2(d[0], d[1]);
            *(float2*)&C[(size_t)(row + 8) * N + col] = make_float2(d[2], d[3]);
        }
    }
}

// ---------------------------------------------------------------------------
// RoPE in-place on Q and K.
// ---------------------------------------------------------------------------
__global__ __launch_bounds__(256) void rope_kernel(float* __restrict__ Q,
                                                   float* __restrict__ K,
                                                   const int* __restrict__ pos) {
    int idx = blockIdx.x * 256 + threadIdx.x;
    int row = idx >> 9;
    int pc = idx & 511;
    int p = pc & 31;
    int s = row & (SEQ - 1);

    float inv = expf((float)p * -0.28782313662425572f);
    float ang = (float)pos[s] * inv;
    float sv, cv;
    sincosf(ang, &sv, &cv);

    size_t off = (size_t)row * D_MODEL + 2 * pc;
    float2 qv = *(float2*)&Q[off];
    float2 kv = *(float2*)&K[off];
    *(float2*)&Q[off] = make_float2(qv.x * cv - qv.y * sv, qv.x * sv + qv.y * cv);
    *(float2*)&K[off] = make_float2(kv.x * cv - kv.y * sv, kv.x * sv + kv.y * cv);
}

// ---------------------------------------------------------------------------
// TF32 tensor-core causal flash attention.
// Grid: (SEQ/128, B*H). Block: 256 threads = 8 warps, warp owns 16 q-rows.
// Bq=128, Bk=64, dk=64. Q frags in registers; K/V(T)/P staged in smem with
// interleaved tf32 fragment layout (pitch 68).
// ---------------------------------------------------------------------------
__global__ __launch_bounds__(256) void attn_tc(const float* __restrict__ Q,
                                               const float* __restrict__ K,
                                               const float* __restrict__ V,
                                               float* __restrict__ O) {
    extern __shared__ unsigned smem_u[];
    unsigned* Ks = smem_u;                 // 64 * 68
    unsigned* Vs = smem_u + 64 * 68;       // 64 * 68 (V transposed)
    unsigned* Psu = smem_u + 2 * 64 * 68;  // 128 * 68 (P tf32 bits / Q staging)
    float* Psf = (float*)Psu;

    const int tid = threadIdx.x;
    const int lane = tid & 31;
    const int w = tid >> 5;
    const int g = lane >> 2;
    const int q = lane & 3;

    const int bh = blockIdx.y;
    const int b = bh >> 4;
    const int h = bh & 15;
    const int qt = (SEQ / 128 - 1) - blockIdx.x;  // heavy tiles first
    const int q0 = qt * 128;

    const float* Qb = Q + (size_t)b * SEQ * D_MODEL + h * DK;
    const float* Kb = K + (size_t)b * SEQ * D_MODEL + h * DK;
    const float* Vb = V + (size_t)b * SEQ * D_MODEL + h * DK;
    float* Ob = O + (size_t)b * SEQ * D_MODEL + h * DK;

    // Stage Q tile (fp32, natural layout) into Ps area
#pragma unroll
    for (int it = 0; it < 8; it++) {
        int idx = tid + it * 256;
        int r = idx >> 4;
        int c = (idx & 15) << 2;
        float4 v = *(const float4*)&Qb[(size_t)(q0 + r) * D_MODEL + c];
        *(float4*)&Psf[r * 68 + c] = v;
    }
    __syncthreads();

    // Extract Q fragments (scale 1/8 folded in), keep in registers
    unsigned qf[8][4];
    {
        int r0 = (16 * w + g) * 68;
        int r1 = (16 * w + g + 8) * 68;
#pragma unroll
        for (int s = 0; s < 8; s++) {
            qf[s][0] = f2tf32(Psf[r0 + 8 * s + q] * 0.125f);
            qf[s][1] = f2tf32(Psf[r1 + 8 * s + q] * 0.125f);
            qf[s][2] = f2tf32(Psf[r0 + 8 * s + q + 4] * 0.125f);
            qf[s][3] = f2tf32(Psf[r1 + 8 * s + q + 4] * 0.125f);
        }
    }

    float oacc[8][4] = {};
    float m0 = -1e30f, m1 = -1e30f, l0 = 0.f, l1 = 0.f;

    const int pr0 = (16 * w + g) * 68;
    const int pr1 = pr0 + 8 * 68;
    const int l0a = 2 * q;           // logical col (c0) within group
    const int l1a = 2 * q + 1;       // logical col (c1)
    const int pa = 2 * (l0a & 3) + (l0a >> 2);  // physical pos for c0
    const int pb = 2 * (l1a & 3) + (l1a >> 2);  // physical pos for c1

    const int nkt = (q0 + 128) >> 6;
    for (int kt = 0; kt < nkt; kt++) {
        const int k0 = kt << 6;
        __syncthreads();   // prev iteration's Ks/Vs reads done

        // K tile (coalesced rows, interleaved tf32 store)
#pragma unroll
        for (int it = 0; it < 4; it++) {
            int idx = tid + it * 256;
            int r = idx >> 4;
            int c = (idx & 15) << 2;
            float4 kv = *(const float4*)&Kb[(size_t)(k0 + r) * D_MODEL + c];
            float e[4] = {kv.x, kv.y, kv.z, kv.w};
#pragma unroll
            for (int j = 0; j < 4; j++) {
                int L = c + j;
                int pos = (L >> 3) * 8 + 2 * (L & 3) + ((L & 7) >> 2);
                Ks[r * 68 + pos] = f2tf32(e[j]);
            }
        }
        // V tile transposed: Vs[dk_col][key interleaved]
#pragma unroll
        for (int it = 0; it < 4; it++) {
            int idx = tid + it * 256;
            int key = idx & 63;
            int c4 = idx >> 6;
            float4 vv = *(const float4*)&Vb[(size_t)(k0 + key) * D_MODEL + 4 * c4];
            int pk = (key >> 3) * 8 + 2 * (key & 3) + ((key & 7) >> 2);
            float e[4] = {vv.x, vv.y, vv.z, vv.w};
#pragma unroll
            for (int j = 0; j < 4; j++)
                Vs[(4 * c4 + j) * 68 + pk] = f2tf32(e[j]);
        }
        __syncthreads();

        // S = Q K^T  (warp: m16 x n64 x k64)
        float sacc[8][4];
#pragma unroll
        for (int j = 0; j < 8; j++)
#pragma unroll
            for (int r = 0; r < 4; r++) sacc[j][r] = 0.f;
#pragma unroll
        for (int j = 0; j < 8; j++) {
            int krow = (j * 8 + g) * 68;
#pragma unroll
            for (int s = 0; s < 8; s++) {
                uint2 bb = *(const uint2*)&Ks[krow + 8 * s + 2 * q];
                MMA_TF32(sacc[j], qf[s], bb);
            }
        }

        // Causal mask (only tiles overlapping the diagonal for this warp)
        if (k0 + 63 > q0 + 16 * w) {
            int row0 = q0 + 16 * w + g;
            int row1 = row0 + 8;
#pragma unroll
            for (int j = 0; j < 8; j++) {
                int c0 = k0 + 8 * j + 2 * q;
                int c1 = c0 + 1;
                if (c0 > row0) sacc[j][0] = -1e30f;
                if (c1 > row0) sacc[j][1] = -1e30f;
                if (c0 > row1) sacc[j][2] = -1e30f;
                if (c1 > row1) sacc[j][3] = -1e30f;
            }
        }

        // Row max (quad shuffle reduce)
        float mx0 = -1e30f, mx1 = -1e30f;
#pragma unroll
        for (int j = 0; j < 8; j++) {
            mx0 = fmaxf(mx0, fmaxf(sacc[j][0], sacc[j][1]));
            mx1 = fmaxf(mx1, fmaxf(sacc[j][2], sacc[j][3]));
        }
        mx0 = fmaxf(mx0, __shfl_xor_sync(0xffffffffu, mx0, 1));
        mx0 = fmaxf(mx0, __shfl_xor_sync(0xffffffffu, mx0, 2));
        mx1 = fmaxf(mx1, __shfl_xor_sync(0xffffffffu, mx1, 1));
        mx1 = fmaxf(mx1, __shfl_xor_sync(0xffffffffu, mx1, 2));

        float mn0 = fmaxf(m0, mx0);
        float mn1 = fmaxf(m1, mx1);
        float rs0 = exp2f((m0 - mn0) * LOG2EF);
        float rs1 = exp2f((m1 - mn1) * LOG2EF);
        m0 = mn0; m1 = mn1;

        float s0 = 0.f, s1 = 0.f;
#pragma unroll
        for (int j = 0; j < 8; j++) {
            float p0 = exp2f((sacc[j][0] - mn0) * LOG2EF);
            float p1 = exp2f((sacc[j][1] - mn0) * LOG2EF);
            float p2 = exp2f((sacc[j][2] - mn1) * LOG2EF);
            float p3 = exp2f((sacc[j][3] - mn1) * LOG2EF);
            s0 += p0 + p1;
            s1 += p2 + p3;
            Psu[pr0 + 8 * j + pa] = f2tf32(p0);
            Psu[pr0 + 8 * j + pb] = f2tf32(p1);
            Psu[pr1 + 8 * j + pa] = f2tf32(p2);
            Psu[pr1 + 8 * j + pb] = f2tf32(p3);
        }
        s0 += __shfl_xor_sync(0xffffffffu, s0, 1);
        s0 += __shfl_xor_sync(0xffffffffu, s0, 2);
        s1 += __shfl_xor_sync(0xffffffffu, s1, 1);
        s1 += __shfl_xor_sync(0xffffffffu, s1, 2);
        l0 = l0 * rs0 + s0;
        l1 = l1 * rs1 + s1;

        // Rescale O accumulators
#pragma unroll
        for (int j = 0; j < 8; j++) {
            oacc[j][0] *= rs0; oacc[j][1] *= rs0;
            oacc[j][2] *= rs1; oacc[j][3] *= rs1;
        }
        __syncwarp();  // Ps rows are per-warp: warp-level visibility suffices

        // O += P V   (warp: m16 x n64 x k64)
#pragma unroll
        for (int s = 0; s < 8; s++) {
            uint2 alo = *(const uint2*)&Psu[pr0 + 8 * s + 2 * q];
            uint2 ahi = *(const uint2*)&Psu[pr1 + 8 * s + 2 * q];
            unsigned af[4] = {alo.x, ahi.x, alo.y, ahi.y};
#pragma unroll
            for (int j = 0; j < 8; j++) {
                uint2 bb = *(const uint2*)&Vs[(j * 8 + g) * 68 + 8 * s + 2 * q];
                MMA_TF32(oacc[j], af, bb);
            }
        }
    }

    // Epilogue
    float inv0 = 1.f / l0;
    float inv1 = 1.f / l1;
    int row0 = q0 + 16 * w + g;
#pragma unroll
    for (int j = 0; j < 8; j++) {
        int col = 8 * j + 2 * q;
        *(float2*)&Ob[(size_t)row0 * D_MODEL + col] =
            make_float2(oacc[j][0] * inv0, oacc[j][1] * inv0);
        *(float2*)&Ob[(size_t)(row0 + 8) * D_MODEL + col] =
            make_float2(oacc[j][2] * inv1, oacc[j][3] * inv1);
    }
}

// ---------------------------------------------------------------------------
extern "C" void kernel_launch(void* const* d_in, const int* in_sizes, int n_in,
                              void* d_out, int out_size) {
    const float* x  = (const float*)d_in[0];
    const int*   ps = (const int*)d_in[1];
    const float* Wq = (const float*)d_in[2];
    const float* Wk = (const float*)d_in[3];
    const float* Wv = (const float*)d_in[4];
    const float* Wo = (const float*)d_in[5];
    float* out = (float*)d_out;

    float *gq, *gk, *gv, *go;
    cudaGetSymbolAddress((void**)&gq, g_Q);
    cudaGetSymbolAddress((void**)&gk, g_K);
    cudaGetSymbolAddress((void**)&gv, g_V);
    cudaGetSymbolAddress((void**)&go, g_O);

    const int attn_smem = 68 * 256 * 4;  // 69632 bytes
    cudaFuncSetAttribute(attn_tc, cudaFuncAttributeMaxDynamicSharedMemorySize,
                         attn_smem);

    dim3 gg(D_MODEL / 128, MROWS / 128);   // (8, 32)
    gemm_tf32<<<gg, 256>>>(x, Wq, gq, MROWS, D_MODEL, D_MODEL);
    gemm_tf32<<<gg, 256>>>(x, Wk, gk, MROWS, D_MODEL, D_MODEL);
    gemm_tf32<<<gg, 256>>>(x, Wv, gv, MROWS, D_MODEL, D_MODEL);

    rope_kernel<<<(MROWS * 512) / 256, 256>>>(gq, gk, ps);

    attn_tc<<<dim3(SEQ / 128, BATCH * NUM_HEADS), 256, attn_smem>>>(gq, gk, gv, go);

    gemm_tf32<<<gg, 256>>>(go, Wo, out, MROWS, D_MODEL, D_MODEL);
}